// round 8
// baseline (speedup 1.0000x reference)
#include <cuda_runtime.h>
#include <cstdint>
#include <math.h>

#define DEPTH   14
#define LEAVES  16384
#define NNODES  32767
#define MEM     512
#define G3      1536
#define WORD    300
#define TAG     100
#define LEAF_IN 400
#define CH_IN   712
#define NCTA    296

// ---------------- scratch (device globals) -----------------------------------
__device__ float g_states[(size_t)NNODES * MEM];
__device__ float g_GiB[(size_t)1024 * 256 * 48];      // blocked odd-row gi preacts
__device__ float g_H [(size_t)(LEAVES / 2) * MEM];    // h1 (row-major)
__device__ float g_H2[(size_t)(LEAVES / 2) * MEM];    // h2 (row-major)
__device__ float g_embsR[(size_t)LEAVES * WORD];
__device__ float g_tagsR[(size_t)NNODES * TAG];
__device__ float g_Wl [(size_t)G3 * LEAF_IN];
__device__ float g_Wci[(size_t)G3 * CH_IN];
__device__ float g_Wch[(size_t)G3 * MEM];
__device__ float g_Wn [(size_t)G3 * MEM];
__device__ unsigned g_epoch = 0;
__device__ unsigned g_count = 0;

__device__ __forceinline__ float sigmoidf(float x) { return 1.0f / (1.0f + expf(-x)); }

__device__ __forceinline__ uint32_t f2tf32(float x) {
    uint32_t r;
    asm("cvt.rna.tf32.f32 %0, %1;" : "=r"(r) : "f"(x));
    return r;
}
__device__ __forceinline__ void mma_tf32(float* c, const uint32_t* a, const uint32_t* b) {
    asm volatile(
        "mma.sync.aligned.m16n8k8.row.col.f32.tf32.tf32.f32 "
        "{%0,%1,%2,%3}, {%4,%5,%6,%7}, {%8,%9}, {%0,%1,%2,%3};"
        : "+f"(c[0]), "+f"(c[1]), "+f"(c[2]), "+f"(c[3])
        : "r"(a[0]), "r"(a[1]), "r"(a[2]), "r"(a[3]), "r"(b[0]), "r"(b[1]));
}
__device__ __forceinline__ void ldsm4(uint32_t* r, uint32_t addr) {
    asm volatile("ldmatrix.sync.aligned.m8n8.x4.shared.b16 {%0,%1,%2,%3}, [%4];"
                 : "=r"(r[0]), "=r"(r[1]), "=r"(r[2]), "=r"(r[3]) : "r"(addr));
}
__device__ __forceinline__ uint32_t smem_u32(const void* p) {
    uint32_t a;
    asm("{ .reg .u64 t; cvta.to.shared.u64 t, %1; cvt.u32.u64 %0, t; }" : "=r"(a) : "l"(p));
    return a;
}
__device__ __forceinline__ void cp16(uint32_t dst, const float* src, int sz) {
    asm volatile("cp.async.cg.shared.global [%0], [%1], 16, %2;"
                 :: "r"(dst), "l"(src), "r"(sz) : "memory");
}
#define CP_COMMIT() asm volatile("cp.async.commit_group;" ::: "memory")
#define CP_WAIT1()  asm volatile("cp.async.wait_group 1;" ::: "memory")

__device__ __forceinline__ float ldcg(const float* p) {
    float v;
    asm volatile("ld.global.cg.f32 %0, [%1];" : "=f"(v) : "l"(p));
    return v;
}
__device__ __forceinline__ float4 ldcg4(const float* p) {
    float4 v;
    asm volatile("ld.global.cg.v4.f32 {%0,%1,%2,%3}, [%4];"
                 : "=f"(v.x), "=f"(v.y), "=f"(v.z), "=f"(v.w) : "l"(p));
    return v;
}

// ---------------- grid barrier (monotonic epoch; replay-safe) ------------------
__device__ __forceinline__ void gbar(unsigned target) {
    __syncthreads();
    if (threadIdx.x == 0) {
        __threadfence();
        unsigned v = atomicAdd(&g_count, 1);
        if (v == NCTA - 1) {
            g_count = 0;
            __threadfence();
            atomicAdd(&g_epoch, 1);
        } else {
            while (*(volatile unsigned*)&g_epoch < target) __nanosleep(32);
        }
        __threadfence();
    }
    __syncthreads();
}

// ---------------- fused GEMM + GRU tile ----------------------------------------
#define AST      36
#define STAGE_B  36864u
#define BOFF     9216u
#define SMEM_SZ  (3 * 36864)

template<int MODE, int K>
__device__ void do_tile(const float* __restrict__ Wr, const float* __restrict__ bi,
                        const float* __restrict__ bh, int M, int nlvl,
                        float* __restrict__ out, int bm, int gk0, float* sm) {
    constexpr int NC = (K + 31) / 32;
    const int tid  = threadIdx.x;
    const int lane = tid & 31;
    const int wid  = tid >> 5;
    const int gID  = lane >> 2, tq = lane & 3;
    const int wmRow = (wid >> 2) * 32;
    const int wk    = (wid & 3) * 16;

    __syncthreads();   // smem reuse across tiles

    float acc[2][6][4];
    #pragma unroll
    for (int a = 0; a < 2; a++)
        #pragma unroll
        for (int b = 0; b < 6; b++)
            #pragma unroll
            for (int c = 0; c < 4; c++) acc[a][b][c] = 0.0f;

    const uint32_t smem_base = smem_u32(sm);
    const int rA0 = tid >> 3;
    const int cq  = (tid & 7) * 4;
    const uint32_t dstA0 = smem_base + 4u * (rA0 * AST + cq);
    const uint32_t dstB0 = smem_base + BOFF + 4u * (rA0 * AST + cq);
    uint32_t offB[6];
    #pragma unroll
    for (int it = 0; it < 6; it++) {
        int rB = rA0 + 32 * it;
        int grow = (rB >> 6) * MEM + gk0 + (rB & 63);
        offB[it] = (uint32_t)grow * K + cq;
    }

    uint32_t aAddr[2];
    #pragma unroll
    for (int mt = 0; mt < 2; mt++)
        aAddr[mt] = smem_base + 4u * ((wmRow + mt * 16 + (lane & 15)) * AST + (lane >> 4) * 4);
    uint32_t bAddr[3];
    #pragma unroll
    for (int g = 0; g < 3; g++)
        bAddr[g] = smem_base + BOFF +
                   4u * ((g * 64 + wk + ((lane >> 4) << 3) + (lane & 7)) * AST + ((lane >> 3) & 1) * 4);

    auto issueA = [&](int kc, uint32_t stN) {
        #pragma unroll
        for (int it = 0; it < 2; it++) {
            const int c4 = kc * 32 + cq;
            const int gm = bm + rA0 + 32 * it;
            const float* p = g_embsR;
            int sz = 0;
            if (MODE == 0) {
                if (gm < M) {
                    if (c4 < WORD)         { p = g_embsR + (size_t)gm * WORD + c4; sz = 16; }
                    else if (c4 < LEAF_IN) { p = g_tagsR + (size_t)(LEAVES - 1 + gm) * TAG + (c4 - WORD); sz = 16; }
                }
            } else if (MODE == 1) {
                if (gm < M) {
                    int pid = (gm >> 1) + nlvl - 1;
                    int ch  = 2 * pid + 1 + (gm & 1);
                    if (c4 < MEM)            { p = g_states + (size_t)ch * MEM + c4; sz = 16; }
                    else if (c4 < MEM + TAG) { p = g_tagsR + (size_t)ch * TAG + (c4 - MEM); sz = 16; }
                    else if (c4 < CH_IN)     { p = g_tagsR + (size_t)pid * TAG + (c4 - MEM - TAG); sz = 16; }
                }
            } else {
                const float* src = (MODE == 2) ? g_H : g_H2;
                if (gm < M && c4 < MEM) { p = src + (size_t)gm * MEM + c4; sz = 16; }
            }
            cp16(dstA0 + stN + it * 4608u, p, sz);
        }
    };
    auto issueB = [&](int kc, uint32_t stN) {
        const int c4 = kc * 32 + cq;
        const int sz = (c4 < K) ? 16 : 0;
        #pragma unroll
        for (int it = 0; it < 6; it++)
            cp16(dstB0 + stN + it * 4608u, Wr + offB[it] + (uint32_t)kc * 32u, sz);
    };

    issueA(0, 0u); issueB(0, 0u); CP_COMMIT();
    if (NC > 1) { issueA(1, STAGE_B); issueB(1, STAGE_B); }
    CP_COMMIT();

    uint32_t stC = 0, stI = 2 * STAGE_B;
    #pragma unroll 1
    for (int kc = 0; kc < NC; kc++) {
        CP_WAIT1();
        __syncthreads();
        if (kc + 2 < NC) { issueA(kc + 2, stI); issueB(kc + 2, stI); }
        CP_COMMIT();
        #pragma unroll
        for (int k8 = 0; k8 < 4; k8++) {
            const uint32_t kb = stC + k8 * 32u;
            uint32_t afr[2][4], bfr[3][4];
            ldsm4(afr[0], aAddr[0] + kb);
            ldsm4(afr[1], aAddr[1] + kb);
            ldsm4(bfr[0], bAddr[0] + kb);
            ldsm4(bfr[1], bAddr[1] + kb);
            ldsm4(bfr[2], bAddr[2] + kb);
            #pragma unroll
            for (int mt = 0; mt < 2; mt++)
                #pragma unroll
                for (int g = 0; g < 3; g++) {
                    mma_tf32(acc[mt][2 * g],     afr[mt], bfr[g]);
                    mma_tf32(acc[mt][2 * g + 1], afr[mt], bfr[g] + 2);
                }
        }
        stC += STAGE_B; if (stC == 3 * STAGE_B) stC = 0;
        stI += STAGE_B; if (stI == 3 * STAGE_B) stI = 0;
    }

    // ---- epilogue ----
    if (MODE == 2) {
        const float* gbase = g_GiB +
            (((size_t)(((bm >> 6) << 3) + (gk0 >> 6)) * 256) + (size_t)tid) * 48;
        #pragma unroll
        for (int mt = 0; mt < 2; mt++) {
            float gi[24];
            #pragma unroll
            for (int q = 0; q < 6; q++) {
                float4 v = ldcg4(gbase + mt * 24 + q * 4);
                gi[q * 4 + 0] = v.x; gi[q * 4 + 1] = v.y;
                gi[q * 4 + 2] = v.z; gi[q * 4 + 3] = v.w;
            }
            #pragma unroll
            for (int kt = 0; kt < 2; kt++)
                #pragma unroll
                for (int j = 0; j < 4; j++) {
                    int row = bm + wmRow + mt * 16 + gID + (j >> 1) * 8;
                    if (row >= M) continue;
                    int kcol = gk0 + wk + kt * 8 + 2 * tq + (j & 1);
                    float r  = sigmoidf(gi[kt * 4 + j]      + acc[mt][kt][j]     + bh[kcol]);
                    float z  = sigmoidf(gi[8 + kt * 4 + j]  + acc[mt][2 + kt][j] + bh[MEM + kcol]);
                    float nn = tanhf(gi[16 + kt * 4 + j] +
                                     r * (acc[mt][4 + kt][j] + bh[2 * MEM + kcol]));
                    g_H2[(size_t)row * MEM + kcol] =
                        (1.0f - z) * nn + z * ldcg(g_H + (size_t)row * MEM + kcol);
                }
        }
    } else {
        #pragma unroll
        for (int mt = 0; mt < 2; mt++)
            #pragma unroll
            for (int kt = 0; kt < 2; kt++)
                #pragma unroll
                for (int j = 0; j < 4; j++) {
                    int row = bm + wmRow + mt * 16 + gID + (j >> 1) * 8;
                    if (row >= M) continue;
                    int kcol = gk0 + wk + kt * 8 + 2 * tq + (j & 1);
                    float aR = acc[mt][kt][j];
                    float aZ = acc[mt][2 + kt][j];
                    float aN = acc[mt][4 + kt][j];
                    if (MODE == 0) {
                        float r  = sigmoidf(aR + bi[kcol] + bh[kcol]);
                        float z  = sigmoidf(aZ + bi[MEM + kcol] + bh[MEM + kcol]);
                        float nn = tanhf(aN + bi[2 * MEM + kcol] + r * bh[2 * MEM + kcol]);
                        g_states[(size_t)(LEAVES - 1 + row) * MEM + kcol] = (1.0f - z) * nn;
                    } else if (MODE == 1) {
                        float giR = aR + bi[kcol], giZ = aZ + bi[MEM + kcol],
                              giN = aN + bi[2 * MEM + kcol];
                        if ((row & 1) == 0) {
                            float r  = sigmoidf(giR + bh[kcol]);
                            float z  = sigmoidf(giZ + bh[MEM + kcol]);
                            float nn = tanhf(giN + r * bh[2 * MEM + kcol]);
                            g_H[(size_t)(row >> 1) * MEM + kcol] = (1.0f - z) * nn;
                        } else {
                            int m = row >> 1;
                            int tile2 = ((m >> 6) << 3) + (gk0 >> 6);
                            int r2 = m & 63, c2 = kcol & 63;
                            int wid2  = ((r2 >> 5) << 2) + (c2 >> 4);
                            int lane2 = (r2 & 7) * 4 + ((c2 >> 1) & 3);
                            int off2  = ((r2 >> 4) & 1) * 24 + ((c2 >> 3) & 1) * 4 +
                                        ((r2 >> 3) & 1) * 2 + (c2 & 1);
                            float* p = g_GiB +
                                ((size_t)(tile2 * 256 + wid2 * 32 + lane2)) * 48 + off2;
                            p[0] = giR; p[8] = giZ; p[16] = giN;
                        }
                    } else {  // MODE 3
                        float r  = sigmoidf(bi[kcol] + aR + bh[kcol]);
                        float z  = sigmoidf(bi[MEM + kcol] + aZ + bh[MEM + kcol]);
                        float nn = tanhf(bi[2 * MEM + kcol] + r * (aN + bh[2 * MEM + kcol]));
                        float st = (1.0f - z) * nn + z * ldcg(g_H2 + (size_t)row * MEM + kcol);
                        g_states[(size_t)(row + nlvl - 1) * MEM + kcol] = st;
                        if (nlvl == 1) out[kcol] = st;
                    }
                }
    }
}

template<int MODE, int K>
__device__ void run_phase(const float* Wr, const float* bi, const float* bh,
                          int M, int nlvl, float* out, float* sm) {
    int mtiles = (M + 63) >> 6;
    int nt = mtiles << 3;
    for (int t = blockIdx.x; t < nt; t += NCTA)
        do_tile<MODE, K>(Wr, bi, bh, M, nlvl, out, (t >> 3) << 6, (t & 7) << 6, sm);
}

// ---------------- prep segment (tf32 rounding, float4) --------------------------
__device__ void cvt_seg(const float* __restrict__ s, float* __restrict__ d, int n4) {
    for (int i = blockIdx.x * blockDim.x + threadIdx.x; i < n4; i += NCTA * 256) {
        float4 v = reinterpret_cast<const float4*>(s)[i];
        v.x = __uint_as_float(f2tf32(v.x));
        v.y = __uint_as_float(f2tf32(v.y));
        v.z = __uint_as_float(f2tf32(v.z));
        v.w = __uint_as_float(f2tf32(v.w));
        reinterpret_cast<float4*>(d)[i] = v;
    }
}

// ---------------- the mega kernel ------------------------------------------------
__global__ __launch_bounds__(256, 2)
void mega(const float* __restrict__ embs, const float* __restrict__ tags,
          const float* __restrict__ leaf_Wi, const float* __restrict__ leaf_bi,
          const float* __restrict__ leaf_bh,
          const float* __restrict__ node_Wh, const float* __restrict__ node_bi,
          const float* __restrict__ node_bh,
          const float* __restrict__ ch_Wi, const float* __restrict__ ch_Wh,
          const float* __restrict__ ch_bi, const float* __restrict__ ch_bh,
          float* __restrict__ out) {
    extern __shared__ float sm[];
    const unsigned base = *(volatile unsigned*)&g_epoch;
    unsigned nb = 0;

    // phase: prep (tf32 rounding)
    cvt_seg(embs,    g_embsR, LEAVES * WORD / 4);
    cvt_seg(tags,    g_tagsR, NNODES * TAG / 4);
    cvt_seg(leaf_Wi, g_Wl,    G3 * LEAF_IN / 4);
    cvt_seg(ch_Wi,   g_Wci,   G3 * CH_IN / 4);
    cvt_seg(ch_Wh,   g_Wch,   G3 * MEM / 4);
    cvt_seg(node_Wh, g_Wn,    G3 * MEM / 4);
    gbar(base + ++nb);

    // phase: leaves
    run_phase<0, LEAF_IN>(g_Wl, leaf_bi, leaf_bh, LEAVES, 0, out, sm);
    gbar(base + ++nb);

    // level ladder
    for (int lvl = DEPTH - 1; lvl >= 0; --lvl) {
        int n = 1 << lvl;
        run_phase<1, CH_IN>(g_Wci, ch_bi, ch_bh, 2 * n, n, out, sm);
        gbar(base + ++nb);
        run_phase<2, MEM>(g_Wch, ch_bi, ch_bh, n, n, out, sm);
        gbar(base + ++nb);
        run_phase<3, MEM>(g_Wn, node_bi, node_bh, n, n, out, sm);
        if (lvl > 0) gbar(base + ++nb);
    }
}

// ---------------- host driver ------------------------------------------------
extern "C" void kernel_launch(void* const* d_in, const int* in_sizes, int n_in,
                              void* d_out, int out_size) {
    const float* embs    = (const float*)d_in[0];
    const float* tags    = (const float*)d_in[1];
    const float* leaf_Wi = (const float*)d_in[2];
    const float* leaf_bi = (const float*)d_in[4];
    const float* leaf_bh = (const float*)d_in[5];
    const float* node_Wh = (const float*)d_in[7];
    const float* node_bi = (const float*)d_in[8];
    const float* node_bh = (const float*)d_in[9];
    const float* ch_Wi   = (const float*)d_in[10];
    const float* ch_Wh   = (const float*)d_in[11];
    const float* ch_bi   = (const float*)d_in[12];
    const float* ch_bh   = (const float*)d_in[13];

    cudaFuncSetAttribute(mega, cudaFuncAttributeMaxDynamicSharedMemorySize, SMEM_SZ);
    mega<<<NCTA, 256, SMEM_SZ>>>(embs, tags, leaf_Wi, leaf_bi, leaf_bh,
                                 node_Wh, node_bi, node_bh,
                                 ch_Wi, ch_Wh, ch_bi, ch_bh, (float*)d_out);
}

// round 9
// speedup vs baseline: 1.0188x; 1.0188x over previous
#include <cuda_runtime.h>
#include <cstdint>
#include <math.h>

#define DEPTH   14
#define LEAVES  16384
#define NNODES  32767
#define MEM     512
#define G3      1536
#define WORD    300
#define TAG     100
#define LEAF_IN 400
#define CH_IN   712
#define NTAIL   16          // persistent tail CTAs (levels with n <= 64)

// ---------------- scratch (device globals) -----------------------------------
__device__ float g_states[(size_t)NNODES * MEM];
__device__ float g_GiB[(size_t)1024 * 256 * 48];      // blocked odd-row gi preacts
__device__ float g_H [(size_t)(LEAVES / 2) * MEM];
__device__ float g_H2[(size_t)(LEAVES / 2) * MEM];
__device__ float g_embsR[(size_t)LEAVES * WORD];
__device__ float g_tagsR[(size_t)NNODES * TAG];
__device__ float g_Wl [(size_t)G3 * LEAF_IN];
__device__ float g_Wci[(size_t)G3 * CH_IN];
__device__ float g_Wch[(size_t)G3 * MEM];
__device__ float g_Wn [(size_t)G3 * MEM];
__device__ unsigned g_epoch = 0;
__device__ unsigned g_count = 0;

__device__ __forceinline__ float sigmoidf(float x) { return 1.0f / (1.0f + expf(-x)); }

__device__ __forceinline__ uint32_t f2tf32(float x) {
    uint32_t r;
    asm("cvt.rna.tf32.f32 %0, %1;" : "=r"(r) : "f"(x));
    return r;
}
__device__ __forceinline__ void mma_tf32(float* c, const uint32_t* a, const uint32_t* b) {
    asm volatile(
        "mma.sync.aligned.m16n8k8.row.col.f32.tf32.tf32.f32 "
        "{%0,%1,%2,%3}, {%4,%5,%6,%7}, {%8,%9}, {%0,%1,%2,%3};"
        : "+f"(c[0]), "+f"(c[1]), "+f"(c[2]), "+f"(c[3])
        : "r"(a[0]), "r"(a[1]), "r"(a[2]), "r"(a[3]), "r"(b[0]), "r"(b[1]));
}
__device__ __forceinline__ void ldsm4(uint32_t* r, uint32_t addr) {
    asm volatile("ldmatrix.sync.aligned.m8n8.x4.shared.b16 {%0,%1,%2,%3}, [%4];"
                 : "=r"(r[0]), "=r"(r[1]), "=r"(r[2]), "=r"(r[3]) : "r"(addr));
}
__device__ __forceinline__ uint32_t smem_u32(const void* p) {
    uint32_t a;
    asm("{ .reg .u64 t; cvta.to.shared.u64 t, %1; cvt.u32.u64 %0, t; }" : "=r"(a) : "l"(p));
    return a;
}
__device__ __forceinline__ void cp16(uint32_t dst, const float* src, int sz) {
    asm volatile("cp.async.cg.shared.global [%0], [%1], 16, %2;"
                 :: "r"(dst), "l"(src), "r"(sz) : "memory");
}
#define CP_COMMIT() asm volatile("cp.async.commit_group;" ::: "memory")
#define CP_WAIT1()  asm volatile("cp.async.wait_group 1;" ::: "memory")

__device__ __forceinline__ float ldcg(const float* p) {
    float v;
    asm volatile("ld.global.cg.f32 %0, [%1];" : "=f"(v) : "l"(p));
    return v;
}
__device__ __forceinline__ float4 ldcg4(const float* p) {
    float4 v;
    asm volatile("ld.global.cg.v4.f32 {%0,%1,%2,%3}, [%4];"
                 : "=f"(v.x), "=f"(v.y), "=f"(v.z), "=f"(v.w) : "l"(p));
    return v;
}

// ---------------- grid barrier for NTAIL CTAs (monotonic epoch) ----------------
__device__ __forceinline__ void gbar(unsigned target) {
    __syncthreads();
    if (threadIdx.x == 0) {
        __threadfence();
        unsigned v = atomicAdd(&g_count, 1);
        if (v == NTAIL - 1) {
            g_count = 0;
            __threadfence();
            atomicAdd(&g_epoch, 1);
        } else {
            while (*(volatile unsigned*)&g_epoch < target) { }
        }
        __threadfence();
    }
    __syncthreads();
}

// ---------------- fused GEMM + GRU tile ----------------------------------------
#define AST      36
#define STAGE_B  36864u
#define BOFF     9216u
#define SMEM_SZ  (3 * 36864)

template<int MODE, int K>
__device__ void do_tile(const float* __restrict__ Wr, const float* __restrict__ bi,
                        const float* __restrict__ bh, int M, int nlvl,
                        float* __restrict__ out, int bm, int gk0, float* sm) {
    constexpr int NC = (K + 31) / 32;
    const int tid  = threadIdx.x;
    const int lane = tid & 31;
    const int wid  = tid >> 5;
    const int gID  = lane >> 2, tq = lane & 3;
    const int wmRow = (wid >> 2) * 32;
    const int wk    = (wid & 3) * 16;

    __syncthreads();   // smem reuse across tiles (persistent tail)

    float acc[2][6][4];
    #pragma unroll
    for (int a = 0; a < 2; a++)
        #pragma unroll
        for (int b = 0; b < 6; b++)
            #pragma unroll
            for (int c = 0; c < 4; c++) acc[a][b][c] = 0.0f;

    const uint32_t smem_base = smem_u32(sm);
    const int rA0 = tid >> 3;
    const int cq  = (tid & 7) * 4;
    const uint32_t dstA0 = smem_base + 4u * (rA0 * AST + cq);
    const uint32_t dstB0 = smem_base + BOFF + 4u * (rA0 * AST + cq);
    uint32_t offB[6];
    #pragma unroll
    for (int it = 0; it < 6; it++) {
        int rB = rA0 + 32 * it;
        int grow = (rB >> 6) * MEM + gk0 + (rB & 63);
        offB[it] = (uint32_t)grow * K + cq;
    }

    uint32_t aAddr[2];
    #pragma unroll
    for (int mt = 0; mt < 2; mt++)
        aAddr[mt] = smem_base + 4u * ((wmRow + mt * 16 + (lane & 15)) * AST + (lane >> 4) * 4);
    uint32_t bAddr[3];
    #pragma unroll
    for (int g = 0; g < 3; g++)
        bAddr[g] = smem_base + BOFF +
                   4u * ((g * 64 + wk + ((lane >> 4) << 3) + (lane & 7)) * AST + ((lane >> 3) & 1) * 4);

    auto issueA = [&](int kc, uint32_t stN) {
        #pragma unroll
        for (int it = 0; it < 2; it++) {
            const int c4 = kc * 32 + cq;
            const int gm = bm + rA0 + 32 * it;
            const float* p = g_embsR;
            int sz = 0;
            if (MODE == 0) {
                if (gm < M) {
                    if (c4 < WORD)         { p = g_embsR + (size_t)gm * WORD + c4; sz = 16; }
                    else if (c4 < LEAF_IN) { p = g_tagsR + (size_t)(LEAVES - 1 + gm) * TAG + (c4 - WORD); sz = 16; }
                }
            } else if (MODE == 1) {
                if (gm < M) {
                    int pid = (gm >> 1) + nlvl - 1;
                    int ch  = 2 * pid + 1 + (gm & 1);
                    if (c4 < MEM)            { p = g_states + (size_t)ch * MEM + c4; sz = 16; }
                    else if (c4 < MEM + TAG) { p = g_tagsR + (size_t)ch * TAG + (c4 - MEM); sz = 16; }
                    else if (c4 < CH_IN)     { p = g_tagsR + (size_t)pid * TAG + (c4 - MEM - TAG); sz = 16; }
                }
            } else {
                const float* src = (MODE == 2) ? g_H : g_H2;
                if (gm < M && c4 < MEM) { p = src + (size_t)gm * MEM + c4; sz = 16; }
            }
            cp16(dstA0 + stN + it * 4608u, p, sz);
        }
    };
    auto issueB = [&](int kc, uint32_t stN) {
        const int c4 = kc * 32 + cq;
        const int sz = (c4 < K) ? 16 : 0;
        #pragma unroll
        for (int it = 0; it < 6; it++)
            cp16(dstB0 + stN + it * 4608u, Wr + offB[it] + (uint32_t)kc * 32u, sz);
    };

    issueA(0, 0u); issueB(0, 0u); CP_COMMIT();
    if (NC > 1) { issueA(1, STAGE_B); issueB(1, STAGE_B); }
    CP_COMMIT();

    uint32_t stC = 0, stI = 2 * STAGE_B;
    #pragma unroll 1
    for (int kc = 0; kc < NC; kc++) {
        CP_WAIT1();
        __syncthreads();
        if (kc + 2 < NC) { issueA(kc + 2, stI); issueB(kc + 2, stI); }
        CP_COMMIT();
        #pragma unroll
        for (int k8 = 0; k8 < 4; k8++) {
            const uint32_t kb = stC + k8 * 32u;
            uint32_t afr[2][4], bfr[3][4];
            ldsm4(afr[0], aAddr[0] + kb);
            ldsm4(afr[1], aAddr[1] + kb);
            ldsm4(bfr[0], bAddr[0] + kb);
            ldsm4(bfr[1], bAddr[1] + kb);
            ldsm4(bfr[2], bAddr[2] + kb);
            #pragma unroll
            for (int mt = 0; mt < 2; mt++)
                #pragma unroll
                for (int g = 0; g < 3; g++) {
                    mma_tf32(acc[mt][2 * g],     afr[mt], bfr[g]);
                    mma_tf32(acc[mt][2 * g + 1], afr[mt], bfr[g] + 2);
                }
        }
        stC += STAGE_B; if (stC == 3 * STAGE_B) stC = 0;
        stI += STAGE_B; if (stI == 3 * STAGE_B) stI = 0;
    }

    // ---- epilogue ----
    if (MODE == 2) {
        const float* gbase = g_GiB +
            (((size_t)(((bm >> 6) << 3) + (gk0 >> 6)) * 256) + (size_t)tid) * 48;
        #pragma unroll
        for (int mt = 0; mt < 2; mt++) {
            float gi[24];
            #pragma unroll
            for (int q = 0; q < 6; q++) {
                float4 v = ldcg4(gbase + mt * 24 + q * 4);
                gi[q * 4 + 0] = v.x; gi[q * 4 + 1] = v.y;
                gi[q * 4 + 2] = v.z; gi[q * 4 + 3] = v.w;
            }
            #pragma unroll
            for (int kt = 0; kt < 2; kt++)
                #pragma unroll
                for (int j = 0; j < 4; j++) {
                    int row = bm + wmRow + mt * 16 + gID + (j >> 1) * 8;
                    if (row >= M) continue;
                    int kcol = gk0 + wk + kt * 8 + 2 * tq + (j & 1);
                    float r  = sigmoidf(gi[kt * 4 + j]      + acc[mt][kt][j]     + bh[kcol]);
                    float z  = sigmoidf(gi[8 + kt * 4 + j]  + acc[mt][2 + kt][j] + bh[MEM + kcol]);
                    float nn = tanhf(gi[16 + kt * 4 + j] +
                                     r * (acc[mt][4 + kt][j] + bh[2 * MEM + kcol]));
                    g_H2[(size_t)row * MEM + kcol] =
                        (1.0f - z) * nn + z * ldcg(g_H + (size_t)row * MEM + kcol);
                }
        }
    } else {
        #pragma unroll
        for (int mt = 0; mt < 2; mt++)
            #pragma unroll
            for (int kt = 0; kt < 2; kt++)
                #pragma unroll
                for (int j = 0; j < 4; j++) {
                    int row = bm + wmRow + mt * 16 + gID + (j >> 1) * 8;
                    if (row >= M) continue;
                    int kcol = gk0 + wk + kt * 8 + 2 * tq + (j & 1);
                    float aR = acc[mt][kt][j];
                    float aZ = acc[mt][2 + kt][j];
                    float aN = acc[mt][4 + kt][j];
                    if (MODE == 0) {
                        float r  = sigmoidf(aR + bi[kcol] + bh[kcol]);
                        float z  = sigmoidf(aZ + bi[MEM + kcol] + bh[MEM + kcol]);
                        float nn = tanhf(aN + bi[2 * MEM + kcol] + r * bh[2 * MEM + kcol]);
                        g_states[(size_t)(LEAVES - 1 + row) * MEM + kcol] = (1.0f - z) * nn;
                    } else if (MODE == 1) {
                        float giR = aR + bi[kcol], giZ = aZ + bi[MEM + kcol],
                              giN = aN + bi[2 * MEM + kcol];
                        if ((row & 1) == 0) {
                            float r  = sigmoidf(giR + bh[kcol]);
                            float z  = sigmoidf(giZ + bh[MEM + kcol]);
                            float nn = tanhf(giN + r * bh[2 * MEM + kcol]);
                            g_H[(size_t)(row >> 1) * MEM + kcol] = (1.0f - z) * nn;
                        } else {
                            int m = row >> 1;
                            int tile2 = ((m >> 6) << 3) + (gk0 >> 6);
                            int r2 = m & 63, c2 = kcol & 63;
                            int wid2  = ((r2 >> 5) << 2) + (c2 >> 4);
                            int lane2 = (r2 & 7) * 4 + ((c2 >> 1) & 3);
                            int off2  = ((r2 >> 4) & 1) * 24 + ((c2 >> 3) & 1) * 4 +
                                        ((r2 >> 3) & 1) * 2 + (c2 & 1);
                            float* p = g_GiB +
                                ((size_t)(tile2 * 256 + wid2 * 32 + lane2)) * 48 + off2;
                            p[0] = giR; p[8] = giZ; p[16] = giN;
                        }
                    } else {  // MODE 3
                        float r  = sigmoidf(bi[kcol] + aR + bh[kcol]);
                        float z  = sigmoidf(bi[MEM + kcol] + aZ + bh[MEM + kcol]);
                        float nn = tanhf(bi[2 * MEM + kcol] + r * (aN + bh[2 * MEM + kcol]));
                        float st = (1.0f - z) * nn + z * ldcg(g_H2 + (size_t)row * MEM + kcol);
                        g_states[(size_t)(row + nlvl - 1) * MEM + kcol] = st;
                        if (nlvl == 1) out[kcol] = st;
                    }
                }
    }
}

// ---------------- big-level kernels (one tile per CTA) --------------------------
template<int MODE, int K>
__global__ __launch_bounds__(256, 2)
void gemm_big(const float* __restrict__ Wr, const float* __restrict__ bi,
              const float* __restrict__ bh, int M, int nlvl, float* __restrict__ out) {
    extern __shared__ float sm[];
    do_tile<MODE, K>(Wr, bi, bh, M, nlvl, out, blockIdx.y * 64, blockIdx.x * 64, sm);
}

// ---------------- persistent tail kernel (levels lvl <= 6) ----------------------
__global__ __launch_bounds__(256, 2)
void tail_kernel(const float* __restrict__ node_bi, const float* __restrict__ node_bh,
                 const float* __restrict__ ch_bi, const float* __restrict__ ch_bh,
                 float* __restrict__ out) {
    extern __shared__ float sm[];
    const unsigned base = *(volatile unsigned*)&g_epoch;
    unsigned nb = 0;
    for (int lvl = 6; lvl >= 0; --lvl) {
        int n = 1 << lvl;
        {   // gemm1: M = 2n
            int nt = (((2 * n) + 63) >> 6) << 3;
            for (int t = blockIdx.x; t < nt; t += NTAIL)
                do_tile<1, CH_IN>(g_Wci, ch_bi, ch_bh, 2 * n, n, out,
                                  (t >> 3) << 6, (t & 7) << 6, sm);
            gbar(base + ++nb);
        }
        {   // gemm2: M = n
            int nt = ((n + 63) >> 6) << 3;
            for (int t = blockIdx.x; t < nt; t += NTAIL)
                do_tile<2, MEM>(g_Wch, ch_bi, ch_bh, n, n, out,
                                (t >> 3) << 6, (t & 7) << 6, sm);
            gbar(base + ++nb);
        }
        {   // gemm3: M = n
            int nt = ((n + 63) >> 6) << 3;
            for (int t = blockIdx.x; t < nt; t += NTAIL)
                do_tile<3, MEM>(g_Wn, node_bi, node_bh, n, n, out,
                                (t >> 3) << 6, (t & 7) << 6, sm);
            if (lvl > 0) gbar(base + ++nb);
        }
    }
}

// ---------------- prep: round weights/embs/tags to tf32 once --------------------
#define N_EMB (LEAVES * WORD)
#define N_TAG (NNODES * TAG)
#define N_WL  (G3 * LEAF_IN)
#define N_WCI (G3 * CH_IN)
#define N_WCH (G3 * MEM)
#define N_TOT ((int64_t)N_EMB + N_TAG + N_WL + N_WCI + 2 * N_WCH)

__global__ void prep_round(const float* __restrict__ embs, const float* __restrict__ tags,
                           const float* __restrict__ lw, const float* __restrict__ cwi,
                           const float* __restrict__ cwh, const float* __restrict__ nw) {
    int64_t i = blockIdx.x * (int64_t)blockDim.x + threadIdx.x;
    int64_t stride = (int64_t)gridDim.x * blockDim.x;
    for (; i < N_TOT; i += stride) {
        int64_t j = i;
        const float* s; float* d;
        if (j < N_EMB)               { s = embs; d = g_embsR; }
        else if ((j -= N_EMB) < N_TAG) { s = tags; d = g_tagsR; }
        else if ((j -= N_TAG) < N_WL)  { s = lw;   d = g_Wl; }
        else if ((j -= N_WL) < N_WCI)  { s = cwi;  d = g_Wci; }
        else if ((j -= N_WCI) < N_WCH) { s = cwh;  d = g_Wch; }
        else { j -= N_WCH;              s = nw;   d = g_Wn; }
        d[j] = __uint_as_float(f2tf32(s[j]));
    }
}

// ---------------- host driver ------------------------------------------------
extern "C" void kernel_launch(void* const* d_in, const int* in_sizes, int n_in,
                              void* d_out, int out_size) {
    const float* embs    = (const float*)d_in[0];
    const float* tags    = (const float*)d_in[1];
    const float* leaf_Wi = (const float*)d_in[2];
    const float* leaf_bi = (const float*)d_in[4];
    const float* leaf_bh = (const float*)d_in[5];
    const float* node_Wh = (const float*)d_in[7];
    const float* node_bi = (const float*)d_in[8];
    const float* node_bh = (const float*)d_in[9];
    const float* ch_Wi   = (const float*)d_in[10];
    const float* ch_Wh   = (const float*)d_in[11];
    const float* ch_bi   = (const float*)d_in[12];
    const float* ch_bh   = (const float*)d_in[13];

    float *pWl, *pWci, *pWch, *pWn;
    cudaGetSymbolAddress((void**)&pWl,  g_Wl);
    cudaGetSymbolAddress((void**)&pWci, g_Wci);
    cudaGetSymbolAddress((void**)&pWch, g_Wch);
    cudaGetSymbolAddress((void**)&pWn,  g_Wn);

    cudaFuncSetAttribute(gemm_big<0,LEAF_IN>, cudaFuncAttributeMaxDynamicSharedMemorySize, SMEM_SZ);
    cudaFuncSetAttribute(gemm_big<1,CH_IN>,   cudaFuncAttributeMaxDynamicSharedMemorySize, SMEM_SZ);
    cudaFuncSetAttribute(gemm_big<2,MEM>,     cudaFuncAttributeMaxDynamicSharedMemorySize, SMEM_SZ);
    cudaFuncSetAttribute(gemm_big<3,MEM>,     cudaFuncAttributeMaxDynamicSharedMemorySize, SMEM_SZ);
    cudaFuncSetAttribute(tail_kernel,         cudaFuncAttributeMaxDynamicSharedMemorySize, SMEM_SZ);

    auto grid = [](int M) { return dim3(MEM / 64, (M + 63) / 64); };
    float* out = (float*)d_out;

    prep_round<<<2048, 256>>>(embs, tags, leaf_Wi, ch_Wi, ch_Wh, node_Wh);

    gemm_big<0,LEAF_IN><<<grid(LEAVES), 256, SMEM_SZ>>>(pWl, leaf_bi, leaf_bh, LEAVES, 0, out);
    for (int lvl = DEPTH - 1; lvl >= 7; --lvl) {
        int n = 1 << lvl;
        gemm_big<1,CH_IN><<<grid(2 * n), 256, SMEM_SZ>>>(pWci, ch_bi, ch_bh, 2 * n, n, out);
        gemm_big<2,MEM><<<grid(n), 256, SMEM_SZ>>>(pWch, ch_bi, ch_bh, n, n, out);
        gemm_big<3,MEM><<<grid(n), 256, SMEM_SZ>>>(pWn, node_bi, node_bh, n, n, out);
    }
    tail_kernel<<<NTAIL, 256, SMEM_SZ>>>(node_bi, node_bh, ch_bi, ch_bh, out);
}